// round 3
// baseline (speedup 1.0000x reference)
#include <cuda_runtime.h>
#include <cuda_bf16.h>
#include <math.h>

// Problem constants
#define BB 4
#define NN 2048
#define VD 256
#define CD 64
#define HH 4
#define DD 64
#define INNER 256
#define ROWS (BB * NN)   // 8192

// ---------------- scratch (device globals; no allocation allowed) ----------
__device__ float g_Vn[ROWS * VD];          // LN(V)
__device__ float g_Cn[ROWS * CD];          // LN(C)
__device__ float g_qkv[ROWS * 2 * INNER];  // rmsnorm(Vn @ W_vqk + b)
__device__ float g_qkc[ROWS * 2 * INNER];  // rmsnorm(Cn @ W_cqk + b)
__device__ float g_vv[ROWS * INNER];
__device__ float g_vc[ROWS * INNER];
__device__ float g_ovp[ROWS * INNER];      // attn @ vv (pre out-proj)
__device__ float g_ocp[ROWS * INNER];      // attn @ vc (pre out-proj)

// ---------------- LayerNorm -------------------------------------------------
template <int DIM>
__global__ void ln_kernel(const float* __restrict__ x, const float* __restrict__ g,
                          const float* __restrict__ b, float* __restrict__ out) {
    constexpr int NW = DIM / 32;
    __shared__ float red[NW];
    int row = blockIdx.x;
    int t = threadIdx.x;
    float v = x[row * DIM + t];

    float s = v;
    #pragma unroll
    for (int o = 16; o; o >>= 1) s += __shfl_xor_sync(0xFFFFFFFFu, s, o);
    if ((t & 31) == 0) red[t >> 5] = s;
    __syncthreads();
    float tot = 0.f;
    #pragma unroll
    for (int i = 0; i < NW; i++) tot += red[i];
    float mean = tot / (float)DIM;
    __syncthreads();

    float d = v - mean;
    float s2 = d * d;
    #pragma unroll
    for (int o = 16; o; o >>= 1) s2 += __shfl_xor_sync(0xFFFFFFFFu, s2, o);
    if ((t & 31) == 0) red[t >> 5] = s2;
    __syncthreads();
    float var = 0.f;
    #pragma unroll
    for (int i = 0; i < NW; i++) var += red[i];
    var /= (float)DIM;

    out[row * DIM + t] = d * rsqrtf(var + 1e-5f) * g[t] + b[t];
}

// ---------------- RMSNorm over 512, in place -------------------------------
__global__ void rms512_kernel(float* __restrict__ x, const float* __restrict__ s) {
    __shared__ float red[8];
    int row = blockIdx.x;
    int t = threadIdx.x;   // 256 threads, 2 elems each
    float* xr = x + row * 512;
    float a = xr[t], c = xr[t + 256];
    float ss = a * a + c * c;
    #pragma unroll
    for (int o = 16; o; o >>= 1) ss += __shfl_xor_sync(0xFFFFFFFFu, ss, o);
    if ((t & 31) == 0) red[t >> 5] = ss;
    __syncthreads();
    float tot = 0.f;
    #pragma unroll
    for (int i = 0; i < 8; i++) tot += red[i];
    float r = rsqrtf(tot / 512.f + 1e-6f);
    xr[t]       = a * r * s[t];
    xr[t + 256] = c * r * s[t + 256];
}

// ---------------- Tiled SGEMM + bias: C = A(MxK) @ W(KxN) + bias -----------
// BM=BN=64, BK=16, 256 threads, 4x4 per thread. M%64==0, N%64==0, K%16==0.
__global__ void gemm_bias_kernel(const float* __restrict__ A, const float* __restrict__ W,
                                 const float* __restrict__ bias, float* __restrict__ C,
                                 int M, int K, int Nc) {
    __shared__ float As[16][64];   // [k][m]
    __shared__ float Ws[16][64];   // [k][n]
    int bm0 = blockIdx.y * 64;
    int bn0 = blockIdx.x * 64;
    int tid = threadIdx.x;
    int tx = tid & 15, ty = tid >> 4;

    float acc[4][4] = {};

    int arow  = tid >> 2;        // 0..63
    int acol4 = (tid & 3) * 4;   // 0,4,8,12
    int wrow  = tid >> 4;        // 0..15
    int wcol4 = (tid & 15) * 4;  // 0..60

    for (int k0 = 0; k0 < K; k0 += 16) {
        float4 av = *(const float4*)&A[(size_t)(bm0 + arow) * K + k0 + acol4];
        As[acol4 + 0][arow] = av.x;
        As[acol4 + 1][arow] = av.y;
        As[acol4 + 2][arow] = av.z;
        As[acol4 + 3][arow] = av.w;
        float4 wv = *(const float4*)&W[(size_t)(k0 + wrow) * Nc + bn0 + wcol4];
        *(float4*)&Ws[wrow][wcol4] = wv;
        __syncthreads();
        #pragma unroll
        for (int k = 0; k < 16; k++) {
            float4 a = *(const float4*)&As[k][ty * 4];
            float4 w = *(const float4*)&Ws[k][tx * 4];
            acc[0][0] += a.x * w.x; acc[0][1] += a.x * w.y; acc[0][2] += a.x * w.z; acc[0][3] += a.x * w.w;
            acc[1][0] += a.y * w.x; acc[1][1] += a.y * w.y; acc[1][2] += a.y * w.z; acc[1][3] += a.y * w.w;
            acc[2][0] += a.z * w.x; acc[2][1] += a.z * w.y; acc[2][2] += a.z * w.z; acc[2][3] += a.z * w.w;
            acc[3][0] += a.w * w.x; acc[3][1] += a.w * w.y; acc[3][2] += a.w * w.z; acc[3][3] += a.w * w.w;
        }
        __syncthreads();
    }
    #pragma unroll
    for (int i = 0; i < 4; i++) {
        int m = bm0 + ty * 4 + i;
        #pragma unroll
        for (int j = 0; j < 4; j++) {
            int n = bn0 + tx * 4 + j;
            C[(size_t)m * Nc + n] = acc[i][j] + bias[n];
        }
    }
}

// ---------------- Attention (flash-style, d=128 = qv||qc, vv||vc) ----------
struct AttnSmem {
    float Qt[128][64];    // transposed: [dim][token], pre-scaled by 1/8
    float Kt[128][64];    // transposed
    float Vs[64][132];    // [token][dim], padded
    float Ss[64][65];     // scores / probs, padded
    float m_s[64];
    float l_s[64];
    float alpha_s[64];
};

__global__ void attn_kernel(const float* __restrict__ qkv, const float* __restrict__ qkc,
                            const float* __restrict__ vv, const float* __restrict__ vc,
                            float* __restrict__ ovp, float* __restrict__ ocp) {
    extern __shared__ char smraw[];
    AttnSmem& sm = *(AttnSmem*)smraw;
    int tid = threadIdx.x;
    int bh = blockIdx.y;
    int b = bh >> 2;       // / HH
    int h = bh & 3;        // % HH
    int n0 = blockIdx.x * 64;
    int tx = tid & 15, ty = tid >> 4;

    const float qscale = 0.125f;  // 1/sqrt(64)

    // Load Q tile transposed & scaled
    for (int idx = tid; idx < 64 * 32; idx += 256) {
        int tok = idx >> 5;
        int q4 = idx & 31;
        int dbase = q4 * 4;
        size_t row = (size_t)(b * NN + n0 + tok);
        float4 v4;
        if (q4 < 16) v4 = *(const float4*)&qkv[row * 512 + h * 64 + dbase];
        else         v4 = *(const float4*)&qkc[row * 512 + h * 64 + (dbase - 64)];
        sm.Qt[dbase + 0][tok] = v4.x * qscale;
        sm.Qt[dbase + 1][tok] = v4.y * qscale;
        sm.Qt[dbase + 2][tok] = v4.z * qscale;
        sm.Qt[dbase + 3][tok] = v4.w * qscale;
    }
    if (tid < 64) { sm.m_s[tid] = -1e30f; sm.l_s[tid] = 0.f; }

    float acc_o[4][8] = {};
    __syncthreads();

    for (int jt = 0; jt < NN / 64; jt++) {
        int kn0 = jt * 64;
        // Load K (transposed) and V tiles
        for (int idx = tid; idx < 64 * 32; idx += 256) {
            int tok = idx >> 5;
            int q4 = idx & 31;
            int dbase = q4 * 4;
            size_t row = (size_t)(b * NN + kn0 + tok);
            float4 k4, v4;
            if (q4 < 16) {
                k4 = *(const float4*)&qkv[row * 512 + 256 + h * 64 + dbase];
                v4 = *(const float4*)&vv[row * 256 + h * 64 + dbase];
            } else {
                k4 = *(const float4*)&qkc[row * 512 + 256 + h * 64 + (dbase - 64)];
                v4 = *(const float4*)&vc[row * 256 + h * 64 + (dbase - 64)];
            }
            sm.Kt[dbase + 0][tok] = k4.x;
            sm.Kt[dbase + 1][tok] = k4.y;
            sm.Kt[dbase + 2][tok] = k4.z;
            sm.Kt[dbase + 3][tok] = k4.w;
            *(float4*)&sm.Vs[tok][dbase] = v4;
        }
        __syncthreads();

        // S = Q_scaled @ K^T   (64x64, k over 128)
        float s_acc[4][4] = {};
        #pragma unroll 8
        for (int k = 0; k < 128; k++) {
            float4 a  = *(const float4*)&sm.Qt[k][ty * 4];
            float4 bb = *(const float4*)&sm.Kt[k][tx * 4];
            s_acc[0][0] += a.x * bb.x; s_acc[0][1] += a.x * bb.y; s_acc[0][2] += a.x * bb.z; s_acc[0][3] += a.x * bb.w;
            s_acc[1][0] += a.y * bb.x; s_acc[1][1] += a.y * bb.y; s_acc[1][2] += a.y * bb.z; s_acc[1][3] += a.y * bb.w;
            s_acc[2][0] += a.z * bb.x; s_acc[2][1] += a.z * bb.y; s_acc[2][2] += a.z * bb.z; s_acc[2][3] += a.z * bb.w;
            s_acc[3][0] += a.w * bb.x; s_acc[3][1] += a.w * bb.y; s_acc[3][2] += a.w * bb.z; s_acc[3][3] += a.w * bb.w;
        }
        #pragma unroll
        for (int i = 0; i < 4; i++)
            #pragma unroll
            for (int j = 0; j < 4; j++)
                sm.Ss[ty * 4 + i][tx * 4 + j] = s_acc[i][j];
        __syncthreads();

        // Online softmax: warp w handles rows w*8 .. w*8+7
        {
            int w = tid >> 5, lane = tid & 31;
            for (int rr = 0; rr < 8; rr++) {
                int r = w * 8 + rr;
                float x0 = sm.Ss[r][lane];
                float x1 = sm.Ss[r][lane + 32];
                float mx = fmaxf(x0, x1);
                #pragma unroll
                for (int o = 16; o; o >>= 1) mx = fmaxf(mx, __shfl_xor_sync(0xFFFFFFFFu, mx, o));
                float m_old = sm.m_s[r];
                float m_new = fmaxf(m_old, mx);
                float p0 = __expf(x0 - m_new);
                float p1 = __expf(x1 - m_new);
                sm.Ss[r][lane] = p0;
                sm.Ss[r][lane + 32] = p1;
                float sum = p0 + p1;
                #pragma unroll
                for (int o = 16; o; o >>= 1) sum += __shfl_xor_sync(0xFFFFFFFFu, sum, o);
                if (lane == 0) {
                    float alpha = __expf(m_old - m_new);
                    sm.alpha_s[r] = alpha;
                    sm.l_s[r] = sm.l_s[r] * alpha + sum;
                    sm.m_s[r] = m_new;
                }
            }
        }
        __syncthreads();

        // Rescale O and accumulate P @ V  (thread: 4 rows x 8 cols)
        {
            float al[4];
            #pragma unroll
            for (int i = 0; i < 4; i++) al[i] = sm.alpha_s[ty * 4 + i];
            #pragma unroll
            for (int i = 0; i < 4; i++)
                #pragma unroll
                for (int j = 0; j < 8; j++) acc_o[i][j] *= al[i];

            #pragma unroll 4
            for (int k = 0; k < 64; k++) {
                float p0 = sm.Ss[ty * 4 + 0][k];
                float p1 = sm.Ss[ty * 4 + 1][k];
                float p2 = sm.Ss[ty * 4 + 2][k];
                float p3 = sm.Ss[ty * 4 + 3][k];
                float4 v0 = *(const float4*)&sm.Vs[k][tx * 8];
                float4 v1 = *(const float4*)&sm.Vs[k][tx * 8 + 4];
                acc_o[0][0] += p0 * v0.x; acc_o[0][1] += p0 * v0.y; acc_o[0][2] += p0 * v0.z; acc_o[0][3] += p0 * v0.w;
                acc_o[0][4] += p0 * v1.x; acc_o[0][5] += p0 * v1.y; acc_o[0][6] += p0 * v1.z; acc_o[0][7] += p0 * v1.w;
                acc_o[1][0] += p1 * v0.x; acc_o[1][1] += p1 * v0.y; acc_o[1][2] += p1 * v0.z; acc_o[1][3] += p1 * v0.w;
                acc_o[1][4] += p1 * v1.x; acc_o[1][5] += p1 * v1.y; acc_o[1][6] += p1 * v1.z; acc_o[1][7] += p1 * v1.w;
                acc_o[2][0] += p2 * v0.x; acc_o[2][1] += p2 * v0.y; acc_o[2][2] += p2 * v0.z; acc_o[2][3] += p2 * v0.w;
                acc_o[2][4] += p2 * v1.x; acc_o[2][5] += p2 * v1.y; acc_o[2][6] += p2 * v1.z; acc_o[2][7] += p2 * v1.w;
                acc_o[3][0] += p3 * v0.x; acc_o[3][1] += p3 * v0.y; acc_o[3][2] += p3 * v0.z; acc_o[3][3] += p3 * v0.w;
                acc_o[3][4] += p3 * v1.x; acc_o[3][5] += p3 * v1.y; acc_o[3][6] += p3 * v1.z; acc_o[3][7] += p3 * v1.w;
            }
        }
        __syncthreads();
    }

    // Epilogue: normalize and write out (split into ovp / ocp halves)
    float linv[4];
    #pragma unroll
    for (int i = 0; i < 4; i++) linv[i] = 1.f / sm.l_s[ty * 4 + i];
    #pragma unroll
    for (int i = 0; i < 4; i++) {
        size_t row = (size_t)(b * NN + n0 + ty * 4 + i);
        #pragma unroll
        for (int j = 0; j < 8; j++) {
            int c = tx * 8 + j;
            float val = acc_o[i][j] * linv[i];
            if (c < 64) ovp[row * 256 + h * 64 + c] = val;
            else        ocp[row * 256 + h * 64 + (c - 64)] = val;
        }
    }
}

// ---------------- launch ----------------------------------------------------
extern "C" void kernel_launch(void* const* d_in, const int* in_sizes, int n_in,
                              void* d_out, int out_size) {
    const float* V     = (const float*)d_in[0];
    const float* C     = (const float*)d_in[1];
    const float* vn_g  = (const float*)d_in[2];
    const float* vn_b  = (const float*)d_in[3];
    const float* cn_g  = (const float*)d_in[4];
    const float* cn_b  = (const float*)d_in[5];
    const float* W_vqk = (const float*)d_in[6];
    const float* b_vqk = (const float*)d_in[7];
    const float* rms_v = (const float*)d_in[8];
    const float* W_cqk = (const float*)d_in[9];
    const float* b_cqk = (const float*)d_in[10];
    const float* rms_c = (const float*)d_in[11];
    const float* W_vv  = (const float*)d_in[12];
    const float* b_vv  = (const float*)d_in[13];
    const float* W_cv  = (const float*)d_in[14];
    const float* b_cv  = (const float*)d_in[15];
    const float* W_ov  = (const float*)d_in[16];
    const float* b_ov  = (const float*)d_in[17];
    const float* W_oc  = (const float*)d_in[18];
    const float* b_oc  = (const float*)d_in[19];

    float* out_v = (float*)d_out;                    // (B,N,VD)
    float* out_c = out_v + (size_t)ROWS * VD;        // (B,N,CD)

    float *pVn, *pCn, *pqkv, *pqkc, *pvv, *pvc, *povp, *pocp;
    cudaGetSymbolAddress((void**)&pVn,  g_Vn);
    cudaGetSymbolAddress((void**)&pCn,  g_Cn);
    cudaGetSymbolAddress((void**)&pqkv, g_qkv);
    cudaGetSymbolAddress((void**)&pqkc, g_qkc);
    cudaGetSymbolAddress((void**)&pvv,  g_vv);
    cudaGetSymbolAddress((void**)&pvc,  g_vc);
    cudaGetSymbolAddress((void**)&povp, g_ovp);
    cudaGetSymbolAddress((void**)&pocp, g_ocp);

    // 1. LayerNorms
    ln_kernel<VD><<<ROWS, VD>>>(V, vn_g, vn_b, pVn);
    ln_kernel<CD><<<ROWS, CD>>>(C, cn_g, cn_b, pCn);

    // 2. Projections
    gemm_bias_kernel<<<dim3(512 / 64, ROWS / 64), 256>>>(pVn, W_vqk, b_vqk, pqkv, ROWS, VD, 512);
    gemm_bias_kernel<<<dim3(512 / 64, ROWS / 64), 256>>>(pCn, W_cqk, b_cqk, pqkc, ROWS, CD, 512);
    gemm_bias_kernel<<<dim3(256 / 64, ROWS / 64), 256>>>(pVn, W_vv,  b_vv,  pvv,  ROWS, VD, 256);
    gemm_bias_kernel<<<dim3(256 / 64, ROWS / 64), 256>>>(pCn, W_cv,  b_cv,  pvc,  ROWS, CD, 256);

    // 3. RMS norms (in place)
    rms512_kernel<<<ROWS, 256>>>(pqkv, rms_v);
    rms512_kernel<<<ROWS, 256>>>(pqkc, rms_c);

    // 4. Attention
    cudaFuncSetAttribute(attn_kernel, cudaFuncAttributeMaxDynamicSharedMemorySize,
                         (int)sizeof(AttnSmem));
    attn_kernel<<<dim3(NN / 64, BB * HH), 256, sizeof(AttnSmem)>>>(pqkv, pqkc, pvv, pvc, povp, pocp);

    // 5. Output projections (write directly into d_out)
    gemm_bias_kernel<<<dim3(256 / 64, ROWS / 64), 256>>>(povp, W_ov, b_ov, out_v, ROWS, INNER, VD);
    gemm_bias_kernel<<<dim3(64 / 64,  ROWS / 64), 256>>>(pocp, W_oc, b_oc, out_c, ROWS, INNER, CD);
}

// round 5
// speedup vs baseline: 2.2420x; 2.2420x over previous
#include <cuda_runtime.h>
#include <cuda_bf16.h>
#include <math.h>
#include <stdint.h>

// Problem constants
#define BB 4
#define NN 2048
#define VD 256
#define CD 64
#define HH 4
#define DD 64
#define INNER 256
#define ROWS (BB * NN)   // 8192

// ---------------- scratch (device globals; no allocation allowed) ----------
__device__ float g_Vn[ROWS * VD];          // LN(V)
__device__ float g_Cn[ROWS * CD];          // LN(C)
__device__ float g_qkv[ROWS * 2 * INNER];  // rmsnorm(Vn @ W_vqk + b)
__device__ float g_qkc[ROWS * 2 * INNER];  // rmsnorm(Cn @ W_cqk + b)
__device__ float g_vv[ROWS * INNER];
__device__ float g_vc[ROWS * INNER];
__device__ float g_ovp[ROWS * INNER];      // attn @ vv (pre out-proj)
__device__ float g_ocp[ROWS * INNER];      // attn @ vc (pre out-proj)

// ---------------- LayerNorm -------------------------------------------------
template <int DIM>
__global__ void ln_kernel(const float* __restrict__ x, const float* __restrict__ g,
                          const float* __restrict__ b, float* __restrict__ out) {
    constexpr int NW = DIM / 32;
    __shared__ float red[NW];
    int row = blockIdx.x;
    int t = threadIdx.x;
    float v = x[row * DIM + t];

    float s = v;
    #pragma unroll
    for (int o = 16; o; o >>= 1) s += __shfl_xor_sync(0xFFFFFFFFu, s, o);
    if ((t & 31) == 0) red[t >> 5] = s;
    __syncthreads();
    float tot = 0.f;
    #pragma unroll
    for (int i = 0; i < NW; i++) tot += red[i];
    float mean = tot / (float)DIM;
    __syncthreads();

    float d = v - mean;
    float s2 = d * d;
    #pragma unroll
    for (int o = 16; o; o >>= 1) s2 += __shfl_xor_sync(0xFFFFFFFFu, s2, o);
    if ((t & 31) == 0) red[t >> 5] = s2;
    __syncthreads();
    float var = 0.f;
    #pragma unroll
    for (int i = 0; i < NW; i++) var += red[i];
    var /= (float)DIM;

    out[row * DIM + t] = d * rsqrtf(var + 1e-5f) * g[t] + b[t];
}

// ---------------- RMSNorm over 512, in place -------------------------------
__global__ void rms512_kernel(float* __restrict__ x, const float* __restrict__ s) {
    __shared__ float red[8];
    int row = blockIdx.x;
    int t = threadIdx.x;   // 256 threads, 2 elems each
    float* xr = x + row * 512;
    float a = xr[t], c = xr[t + 256];
    float ss = a * a + c * c;
    #pragma unroll
    for (int o = 16; o; o >>= 1) ss += __shfl_xor_sync(0xFFFFFFFFu, ss, o);
    if ((t & 31) == 0) red[t >> 5] = ss;
    __syncthreads();
    float tot = 0.f;
    #pragma unroll
    for (int i = 0; i < 8; i++) tot += red[i];
    float r = rsqrtf(tot / 512.f + 1e-6f);
    xr[t]       = a * r * s[t];
    xr[t + 256] = c * r * s[t + 256];
}

// ---------------- Tiled SGEMM + bias: C = A(MxK) @ W(KxN) + bias -----------
__global__ void gemm_bias_kernel(const float* __restrict__ A, const float* __restrict__ W,
                                 const float* __restrict__ bias, float* __restrict__ C,
                                 int M, int K, int Nc) {
    __shared__ float As[16][64];   // [k][m]
    __shared__ float Ws[16][64];   // [k][n]
    int bm0 = blockIdx.y * 64;
    int bn0 = blockIdx.x * 64;
    int tid = threadIdx.x;
    int tx = tid & 15, ty = tid >> 4;

    float acc[4][4] = {};

    int arow  = tid >> 2;
    int acol4 = (tid & 3) * 4;
    int wrow  = tid >> 4;
    int wcol4 = (tid & 15) * 4;

    for (int k0 = 0; k0 < K; k0 += 16) {
        float4 av = *(const float4*)&A[(size_t)(bm0 + arow) * K + k0 + acol4];
        As[acol4 + 0][arow] = av.x;
        As[acol4 + 1][arow] = av.y;
        As[acol4 + 2][arow] = av.z;
        As[acol4 + 3][arow] = av.w;
        float4 wv = *(const float4*)&W[(size_t)(k0 + wrow) * Nc + bn0 + wcol4];
        *(float4*)&Ws[wrow][wcol4] = wv;
        __syncthreads();
        #pragma unroll
        for (int k = 0; k < 16; k++) {
            float4 a = *(const float4*)&As[k][ty * 4];
            float4 w = *(const float4*)&Ws[k][tx * 4];
            acc[0][0] += a.x * w.x; acc[0][1] += a.x * w.y; acc[0][2] += a.x * w.z; acc[0][3] += a.x * w.w;
            acc[1][0] += a.y * w.x; acc[1][1] += a.y * w.y; acc[1][2] += a.y * w.z; acc[1][3] += a.y * w.w;
            acc[2][0] += a.z * w.x; acc[2][1] += a.z * w.y; acc[2][2] += a.z * w.z; acc[2][3] += a.z * w.w;
            acc[3][0] += a.w * w.x; acc[3][1] += a.w * w.y; acc[3][2] += a.w * w.z; acc[3][3] += a.w * w.w;
        }
        __syncthreads();
    }
    #pragma unroll
    for (int i = 0; i < 4; i++) {
        int m = bm0 + ty * 4 + i;
        #pragma unroll
        for (int j = 0; j < 4; j++) {
            int n = bn0 + tx * 4 + j;
            C[(size_t)m * Nc + n] = acc[i][j] + bias[n];
        }
    }
}

// ---------------- Tensor-core attention (split-bf16 x3, flash-style) -------
// d=128 (qv||qc), TQ=TK=64, 256 threads = 8 warps arranged 2(m) x 4(n).

#define LDSM_X4(r0,r1,r2,r3,addr) \
    asm volatile("ldmatrix.sync.aligned.m8n8.x4.shared.b16 {%0,%1,%2,%3}, [%4];" \
        : "=r"(r0),"=r"(r1),"=r"(r2),"=r"(r3) : "r"(addr))

#define LDSM_X4_T(r0,r1,r2,r3,addr) \
    asm volatile("ldmatrix.sync.aligned.m8n8.x4.trans.shared.b16 {%0,%1,%2,%3}, [%4];" \
        : "=r"(r0),"=r"(r1),"=r"(r2),"=r"(r3) : "r"(addr))

#define MMA_BF16(C, A, b0_, b1_) \
    asm volatile("mma.sync.aligned.m16n8k16.row.col.f32.bf16.bf16.f32 " \
        "{%0,%1,%2,%3}, {%4,%5,%6,%7}, {%8,%9}, {%0,%1,%2,%3};" \
        : "+f"((C)[0]), "+f"((C)[1]), "+f"((C)[2]), "+f"((C)[3]) \
        : "r"((A)[0]), "r"((A)[1]), "r"((A)[2]), "r"((A)[3]), "r"(b0_), "r"(b1_))

struct AttnSmem {
    __nv_bfloat16 Qh[64][136];
    __nv_bfloat16 Ql[64][136];
    __nv_bfloat16 Kh[64][136];
    __nv_bfloat16 Kl[64][136];
    __nv_bfloat16 Vh[64][136];
    __nv_bfloat16 Vl[64][136];
    float Ss[64][68];
    __nv_bfloat16 Ph[64][72];
    __nv_bfloat16 Pl[64][72];
    float m_s[64];
    float l_s[64];
    float alpha_s[64];
};

static __device__ __forceinline__ uint32_t smem_u32(const void* p) {
    return (uint32_t)__cvta_generic_to_shared(p);
}

static __device__ __forceinline__ void split_store4(__nv_bfloat16* hi, __nv_bfloat16* lo, float4 v) {
    float hx = __bfloat162float(__float2bfloat16_rn(v.x));
    float hy = __bfloat162float(__float2bfloat16_rn(v.y));
    float hz = __bfloat162float(__float2bfloat16_rn(v.z));
    float hw = __bfloat162float(__float2bfloat16_rn(v.w));
    __nv_bfloat162 h01 = __floats2bfloat162_rn(hx, hy);
    __nv_bfloat162 h23 = __floats2bfloat162_rn(hz, hw);
    __nv_bfloat162 l01 = __floats2bfloat162_rn(v.x - hx, v.y - hy);
    __nv_bfloat162 l23 = __floats2bfloat162_rn(v.z - hz, v.w - hw);
    *(__nv_bfloat162*)&hi[0] = h01;
    *(__nv_bfloat162*)&hi[2] = h23;
    *(__nv_bfloat162*)&lo[0] = l01;
    *(__nv_bfloat162*)&lo[2] = l23;
}

__global__ void __launch_bounds__(256, 1)
attn_kernel(const float* __restrict__ qkv, const float* __restrict__ qkc,
            const float* __restrict__ vv, const float* __restrict__ vc,
            float* __restrict__ ovp, float* __restrict__ ocp) {
    extern __shared__ char smraw[];
    AttnSmem& sm = *(AttnSmem*)smraw;
    int tid = threadIdx.x;
    int lane = tid & 31;
    int w = tid >> 5;
    int wm = w >> 2;          // 0..1
    int wn = w & 3;           // 0..3
    int m0 = wm * 32;
    int n0s = wn * 16;        // S columns for this warp
    int cw0 = wn * 32;        // O columns for this warp
    int g = lane >> 2, t4 = lane & 3;

    int bh = blockIdx.y;
    int b = bh >> 2;
    int h = bh & 3;
    int n0q = blockIdx.x * 64;

    const float qscale = 0.125f;  // 1/sqrt(64)

    // ---- Load + split Q tile ----
    for (int idx = tid; idx < 64 * 32; idx += 256) {
        int tok = idx >> 5;
        int q4 = idx & 31;
        int dbase = q4 * 4;
        size_t row = (size_t)(b * NN + n0q + tok);
        float4 v4;
        if (q4 < 16) v4 = *(const float4*)&qkv[row * 512 + h * 64 + dbase];
        else         v4 = *(const float4*)&qkc[row * 512 + h * 64 + (dbase - 64)];
        v4.x *= qscale; v4.y *= qscale; v4.z *= qscale; v4.w *= qscale;
        split_store4(&sm.Qh[tok][dbase], &sm.Ql[tok][dbase], v4);
    }
    if (tid < 64) { sm.m_s[tid] = -1e30f; sm.l_s[tid] = 0.f; }

    float cO[2][4][4] = {};
    __syncthreads();

    for (int jt = 0; jt < NN / 64; jt++) {
        int kn0 = jt * 64;
        // ---- Load + split K, V tiles ----
        for (int idx = tid; idx < 64 * 32; idx += 256) {
            int tok = idx >> 5;
            int q4 = idx & 31;
            int dbase = q4 * 4;
            size_t row = (size_t)(b * NN + kn0 + tok);
            float4 k4, v4;
            if (q4 < 16) {
                k4 = *(const float4*)&qkv[row * 512 + 256 + h * 64 + dbase];
                v4 = *(const float4*)&vv[row * 256 + h * 64 + dbase];
            } else {
                k4 = *(const float4*)&qkc[row * 512 + 256 + h * 64 + (dbase - 64)];
                v4 = *(const float4*)&vc[row * 256 + h * 64 + (dbase - 64)];
            }
            split_store4(&sm.Kh[tok][dbase], &sm.Kl[tok][dbase], k4);
            split_store4(&sm.Vh[tok][dbase], &sm.Vl[tok][dbase], v4);
        }
        __syncthreads();

        // ---- S = Q @ K^T via split-bf16 mma ----
        float cS[2][2][4] = {};
        const uint32_t HL_QK = (uint32_t)(64 * 136 * sizeof(__nv_bfloat16));  // Qh->Ql, Kh->Kl
        #pragma unroll
        for (int kk = 0; kk < 8; kk++) {
            int k0 = kk * 16;
            uint32_t ah[2][4], al[2][4];
            #pragma unroll
            for (int mt = 0; mt < 2; mt++) {
                uint32_t addr = smem_u32(&sm.Qh[m0 + mt * 16 + (lane & 15)][k0 + (lane >> 4) * 8]);
                LDSM_X4(ah[mt][0], ah[mt][1], ah[mt][2], ah[mt][3], addr);
                LDSM_X4(al[mt][0], al[mt][1], al[mt][2], al[mt][3], addr + HL_QK);
            }
            uint32_t bh0, bh1, bh2, bh3, bl0, bl1, bl2, bl3;
            uint32_t baddr = smem_u32(&sm.Kh[n0s + ((lane >> 4) & 1) * 8 + (lane & 7)]
                                            [k0 + ((lane >> 3) & 1) * 8]);
            LDSM_X4(bh0, bh1, bh2, bh3, baddr);
            LDSM_X4(bl0, bl1, bl2, bl3, baddr + HL_QK);
            #pragma unroll
            for (int mt = 0; mt < 2; mt++) {
                MMA_BF16(cS[mt][0], ah[mt], bh0, bh1);
                MMA_BF16(cS[mt][0], ah[mt], bl0, bl1);
                MMA_BF16(cS[mt][0], al[mt], bh0, bh1);
                MMA_BF16(cS[mt][1], ah[mt], bh2, bh3);
                MMA_BF16(cS[mt][1], ah[mt], bl2, bl3);
                MMA_BF16(cS[mt][1], al[mt], bh2, bh3);
            }
        }
        // write S to smem
        #pragma unroll
        for (int mt = 0; mt < 2; mt++) {
            #pragma unroll
            for (int nf = 0; nf < 2; nf++) {
                int r0 = m0 + mt * 16 + g;
                int c = n0s + nf * 8 + t4 * 2;
                sm.Ss[r0][c]     = cS[mt][nf][0];
                sm.Ss[r0][c + 1] = cS[mt][nf][1];
                sm.Ss[r0 + 8][c]     = cS[mt][nf][2];
                sm.Ss[r0 + 8][c + 1] = cS[mt][nf][3];
            }
        }
        __syncthreads();

        // ---- Online softmax: warp w handles rows w*8 .. w*8+7, write Ph/Pl ----
        #pragma unroll
        for (int rr = 0; rr < 8; rr++) {
            int r = w * 8 + rr;
            float x0 = sm.Ss[r][lane];
            float x1 = sm.Ss[r][lane + 32];
            float mx = fmaxf(x0, x1);
            #pragma unroll
            for (int o = 16; o; o >>= 1) mx = fmaxf(mx, __shfl_xor_sync(0xFFFFFFFFu, mx, o));
            float m_old = sm.m_s[r];
            float m_new = fmaxf(m_old, mx);
            float p0 = __expf(x0 - m_new);
            float p1 = __expf(x1 - m_new);
            float p0h = __bfloat162float(__float2bfloat16_rn(p0));
            float p1h = __bfloat162float(__float2bfloat16_rn(p1));
            sm.Ph[r][lane]      = __float2bfloat16_rn(p0h);
            sm.Ph[r][lane + 32] = __float2bfloat16_rn(p1h);
            sm.Pl[r][lane]      = __float2bfloat16_rn(p0 - p0h);
            sm.Pl[r][lane + 32] = __float2bfloat16_rn(p1 - p1h);
            float sum = p0 + p1;
            #pragma unroll
            for (int o = 16; o; o >>= 1) sum += __shfl_xor_sync(0xFFFFFFFFu, sum, o);
            if (lane == 0) {
                float alpha = __expf(m_old - m_new);
                sm.alpha_s[r] = alpha;
                sm.l_s[r] = sm.l_s[r] * alpha + sum;
                sm.m_s[r] = m_new;
            }
        }
        __syncthreads();

        // ---- Rescale O accumulators by alpha ----
        #pragma unroll
        for (int mt = 0; mt < 2; mt++) {
            float al0 = sm.alpha_s[m0 + mt * 16 + g];
            float al1 = sm.alpha_s[m0 + mt * 16 + 8 + g];
            #pragma unroll
            for (int nf = 0; nf < 4; nf++) {
                cO[mt][nf][0] *= al0; cO[mt][nf][1] *= al0;
                cO[mt][nf][2] *= al1; cO[mt][nf][3] *= al1;
            }
        }

        // ---- O += P @ V via split-bf16 mma ----
        const uint32_t HL_P = (uint32_t)(64 * 72 * sizeof(__nv_bfloat16));   // Ph->Pl
        const uint32_t HL_V = (uint32_t)(64 * 136 * sizeof(__nv_bfloat16));  // Vh->Vl
        #pragma unroll
        for (int kk = 0; kk < 4; kk++) {
            int k0 = kk * 16;
            uint32_t ah[2][4], al[2][4];
            #pragma unroll
            for (int mt = 0; mt < 2; mt++) {
                uint32_t addr = smem_u32(&sm.Ph[m0 + mt * 16 + (lane & 15)][k0 + (lane >> 4) * 8]);
                LDSM_X4(ah[mt][0], ah[mt][1], ah[mt][2], ah[mt][3], addr);
                LDSM_X4(al[mt][0], al[mt][1], al[mt][2], al[mt][3], addr + HL_P);
            }
            uint32_t bhv[2][4], blv[2][4];
            #pragma unroll
            for (int nh = 0; nh < 2; nh++) {
                uint32_t addr = smem_u32(&sm.Vh[k0 + ((lane >> 3) & 1) * 8 + (lane & 7)]
                                               [cw0 + nh * 16 + (lane >> 4) * 8]);
                LDSM_X4_T(bhv[nh][0], bhv[nh][1], bhv[nh][2], bhv[nh][3], addr);
                LDSM_X4_T(blv[nh][0], blv[nh][1], blv[nh][2], blv[nh][3], addr + HL_V);
            }
            #pragma unroll
            for (int mt = 0; mt < 2; mt++) {
                #pragma unroll
                for (int nf = 0; nf < 4; nf++) {
                    int nh = nf >> 1, sub = nf & 1;
                    MMA_BF16(cO[mt][nf], ah[mt], bhv[nh][sub * 2], bhv[nh][sub * 2 + 1]);
                    MMA_BF16(cO[mt][nf], ah[mt], blv[nh][sub * 2], blv[nh][sub * 2 + 1]);
                    MMA_BF16(cO[mt][nf], al[mt], bhv[nh][sub * 2], bhv[nh][sub * 2 + 1]);
                }
            }
        }
        __syncthreads();
    }

    // ---- Epilogue: normalize, write ovp / ocp ----
    #pragma unroll
    for (int mt = 0; mt < 2; mt++) {
        float li0 = 1.f / sm.l_s[m0 + mt * 16 + g];
        float li1 = 1.f / sm.l_s[m0 + mt * 16 + 8 + g];
        size_t row0 = (size_t)(b * NN + n0q + m0 + mt * 16 + g);
        size_t row1 = row0 + 8;
        #pragma unroll
        for (int nf = 0; nf < 4; nf++) {
            int c = cw0 + nf * 8 + t4 * 2;
            float2 o0 = make_float2(cO[mt][nf][0] * li0, cO[mt][nf][1] * li0);
            float2 o1 = make_float2(cO[mt][nf][2] * li1, cO[mt][nf][3] * li1);
            if (c < 64) {
                *(float2*)&ovp[row0 * 256 + h * 64 + c] = o0;
                *(float2*)&ovp[row1 * 256 + h * 64 + c] = o1;
            } else {
                *(float2*)&ocp[row0 * 256 + h * 64 + (c - 64)] = o0;
                *(float2*)&ocp[row1 * 256 + h * 64 + (c - 64)] = o1;
            }
        }
    }
}

// ---------------- launch ----------------------------------------------------
extern "C" void kernel_launch(void* const* d_in, const int* in_sizes, int n_in,
                              void* d_out, int out_size) {
    const float* V     = (const float*)d_in[0];
    const float* C     = (const float*)d_in[1];
    const float* vn_g  = (const float*)d_in[2];
    const float* vn_b  = (const float*)d_in[3];
    const float* cn_g  = (const float*)d_in[4];
    const float* cn_b  = (const float*)d_in[5];
    const float* W_vqk = (const float*)d_in[6];
    const float* b_vqk = (const float*)d_in[7];
    const float* rms_v = (const float*)d_in[8];
    const float* W_cqk = (const float*)d_in[9];
    const float* b_cqk = (const float*)d_in[10];
    const float* rms_c = (const float*)d_in[11];
    const float* W_vv  = (const float*)d_in[12];
    const float* b_vv  = (const float*)d_in[13];
    const float* W_cv  = (const float*)d_in[14];
    const float* b_cv  = (const float*)d_in[15];
    const float* W_ov  = (const float*)d_in[16];
    const float* b_ov  = (const float*)d_in[17];
    const float* W_oc  = (const float*)d_in[18];
    const float* b_oc  = (const float*)d_in[19];

    float* out_v = (float*)d_out;                    // (B,N,VD)
    float* out_c = out_v + (size_t)ROWS * VD;        // (B,N,CD)

    float *pVn, *pCn, *pqkv, *pqkc, *pvv, *pvc, *povp, *pocp;
    cudaGetSymbolAddress((void**)&pVn,  g_Vn);
    cudaGetSymbolAddress((void**)&pCn,  g_Cn);
    cudaGetSymbolAddress((void**)&pqkv, g_qkv);
    cudaGetSymbolAddress((void**)&pqkc, g_qkc);
    cudaGetSymbolAddress((void**)&pvv,  g_vv);
    cudaGetSymbolAddress((void**)&pvc,  g_vc);
    cudaGetSymbolAddress((void**)&povp, g_ovp);
    cudaGetSymbolAddress((void**)&pocp, g_ocp);

    // 1. LayerNorms
    ln_kernel<VD><<<ROWS, VD>>>(V, vn_g, vn_b, pVn);
    ln_kernel<CD><<<ROWS, CD>>>(C, cn_g, cn_b, pCn);

    // 2. Projections
    gemm_bias_kernel<<<dim3(512 / 64, ROWS / 64), 256>>>(pVn, W_vqk, b_vqk, pqkv, ROWS, VD, 512);
    gemm_bias_kernel<<<dim3(512 / 64, ROWS / 64), 256>>>(pCn, W_cqk, b_cqk, pqkc, ROWS, CD, 512);
    gemm_bias_kernel<<<dim3(256 / 64, ROWS / 64), 256>>>(pVn, W_vv,  b_vv,  pvv,  ROWS, VD, 256);
    gemm_bias_kernel<<<dim3(256 / 64, ROWS / 64), 256>>>(pCn, W_cv,  b_cv,  pvc,  ROWS, CD, 256);

    // 3. RMS norms (in place)
    rms512_kernel<<<ROWS, 256>>>(pqkv, rms_v);
    rms512_kernel<<<ROWS, 256>>>(pqkc, rms_c);

    // 4. Attention (tensor cores, split-bf16)
    cudaFuncSetAttribute(attn_kernel, cudaFuncAttributeMaxDynamicSharedMemorySize,
                         (int)sizeof(AttnSmem));
    attn_kernel<<<dim3(NN / 64, BB * HH), 256, sizeof(AttnSmem)>>>(pqkv, pqkc, pvv, pvc, povp, pocp);

    // 5. Output projections (write directly into d_out)
    gemm_bias_kernel<<<dim3(256 / 64, ROWS / 64), 256>>>(povp, W_ov, b_ov, out_v, ROWS, INNER, VD);
    gemm_bias_kernel<<<dim3(64 / 64,  ROWS / 64), 256>>>(pocp, W_oc, b_oc, out_c, ROWS, INNER, CD);
}